// round 16
// baseline (speedup 1.0000x reference)
#include <cuda_runtime.h>
#include <cstdint>

// Problem constants
#define BB   128   // batch
#define LL   196   // encoder length
#define EE   2048  // encoder dim
#define DD   1024  // decoder dim
#define AA   1024  // attention dim
#define USPLIT 8   // split-K of the u GEMM -> 32x8 = 256 CTAs
#define PDEPTH 3   // per-pair pipeline depth (row slots) in fused kernel

// ---------------- device scratch (no allocations allowed) ----------------
// Lifecycle per run: decq GEMM zeroes g_fpart/g_fden (for fused's red.add);
// context GEMM zeroes g_decq/g_u (for next run's GEMM red.add).
// All are zero at module load, so the first run is consistent too.
__device__ float g_decq[BB * AA];        // Wd @ h + bd           [128,1024]
__device__ float g_u[BB * EE];           // dec_q @ Wq            [128,2048]
__device__ float g_fpart[BB * EE];       // fused weighted sums (unnormalized)
__device__ float g_fden[BB];             // fused denominators

// ---------------- helpers ----------------
__device__ __forceinline__ void redadd(float* p, float v) {
    asm volatile("red.global.add.f32 [%0], %1;" :: "l"(p), "f"(v) : "memory");
}
__device__ __forceinline__ void redadd2(float* p, float a, float b) {
    asm volatile("red.global.add.v2.f32 [%0], {%1, %2};"
                 :: "l"(p), "f"(a), "f"(b) : "memory");
}

__device__ __forceinline__ void pack2_bf(float x0, float x1,
                                         uint32_t& wh, uint32_t& wl) {
    asm("cvt.rn.bf16x2.f32 %0, %1, %2;" : "=r"(wh) : "f"(x1), "f"(x0));
    float h0 = __uint_as_float(wh << 16);
    float h1 = __uint_as_float(wh & 0xffff0000u);
    float l0 = x0 - h0;
    float l1 = x1 - h1;
    asm("cvt.rn.bf16x2.f32 %0, %1, %2;" : "=r"(wl) : "f"(l1), "f"(l0));
}

__device__ __forceinline__ void mma_bf16(float* c, const uint32_t* a,
                                         uint32_t b0, uint32_t b1) {
    asm volatile(
        "mma.sync.aligned.m16n8k16.row.col.f32.bf16.bf16.f32 "
        "{%0,%1,%2,%3}, {%4,%5,%6,%7}, {%8,%9}, {%0,%1,%2,%3};"
        : "+f"(c[0]), "+f"(c[1]), "+f"(c[2]), "+f"(c[3])
        : "r"(a[0]), "r"(a[1]), "r"(a[2]), "r"(a[3]), "r"(b0), "r"(b1));
}

// Smem: bf16 hi/lo planes (double buffered) + raw fp32 cp.async staging
// (2 stages). Raw slots are PER-THREAD disjoint and self-targeted.
struct SmemGemm {
    uint32_t Ah[2][128][20];   // 20.0 KB
    uint32_t Al[2][128][20];   // 20.0 KB
    uint32_t Bp[2][16 * 132];  // 16.5 KB
    float4 rawA[2][1024];      // 32 KB : A tile 128x32 fp32
    float4 rawB[2][512];       // 16 KB : B tile 32x64 fp32
};

// =====================================================================
// Tensor-core bf16x3 GEMM, cp.async-staged, ATOMIC (v2) split-K epilogue:
//   dest[m][n] += sum_{k in chunk} X[m,k] * W(k,n)  (+ bias on ky==0 split)
//   NN=true : W is [K,N] row-major;  NN=false: W is [N,K] row-major
// XSEL: 0 -> X param, 1 -> g_decq, 2 -> g_fpart (scale by 1/den at EPILOGUE)
// OUTSEL: 0 -> outp param, 1 -> g_decq, 2 -> g_u
// CLEANSEL: 0 none; 1 zero g_fpart+g_fden; 2 zero g_decq+g_u.
//   (grids are 256 CTAs -> 65536 threads for the CLEAN mappings)
// =====================================================================
template <bool NN, int XSEL, int OUTSEL, int CLEANSEL>
__global__ void __launch_bounds__(256, 2)
gemm_tc(const float* __restrict__ Xp, const float* __restrict__ W,
        float* __restrict__ outp, const float* __restrict__ bias,
        int K, int N, int kchunk) {
    extern __shared__ SmemGemm sm_g[];
    SmemGemm* s = sm_g;

    const float* X = (XSEL == 1) ? (const float*)g_decq
                   : (XSEL == 2) ? (const float*)g_fpart : Xp;

    const int t     = threadIdx.x;
    const int warp  = t >> 5;
    const int lane  = t & 31;
    const int group = lane >> 2;
    const int tg    = lane & 3;
    const int wm    = warp & 3;
    const int wn    = warp >> 2;
    const int n0    = blockIdx.x * 64;
    const int ky    = blockIdx.y;
    const int k0    = ky * kchunk;

    float c[2][4][4];
#pragma unroll
    for (int mi = 0; mi < 2; mi++)
#pragma unroll
        for (int ni = 0; ni < 4; ni++)
#pragma unroll
            for (int r = 0; r < 4; r++) c[mi][ni][r] = 0.f;

    // ---- cp.async fill of raw stage st with tile at kt (self-targeted)
    auto fillRaw = [&](int st, int kt) {
#pragma unroll
        for (int j = 0; j < 4; j++) {
            const int idx = t + 256 * j;
            const int row = idx >> 3;
            const int kq  = idx & 7;
            const float* src = X + (size_t)row * K + kt + kq * 4;
            uint32_t sa = (uint32_t)__cvta_generic_to_shared(&s->rawA[st][idx]);
            asm volatile("cp.async.cg.shared.global [%0], [%1], 16;\n"
                         :: "r"(sa), "l"(src));
        }
        if (NN) {
            const int kp = t >> 4;
            const int nq = t & 15;
            const float* s0 = W + (size_t)(kt + 2 * kp) * N + n0 + nq * 4;
            const float* s1 = W + (size_t)(kt + 2 * kp + 1) * N + n0 + nq * 4;
            uint32_t b0 = (uint32_t)__cvta_generic_to_shared(&s->rawB[st][t]);
            uint32_t b1 = (uint32_t)__cvta_generic_to_shared(&s->rawB[st][t + 256]);
            asm volatile("cp.async.cg.shared.global [%0], [%1], 16;\n" :: "r"(b0), "l"(s0));
            asm volatile("cp.async.cg.shared.global [%0], [%1], 16;\n" :: "r"(b1), "l"(s1));
        } else {
#pragma unroll
            for (int j = 0; j < 2; j++) {
                const int idx = t + 256 * j;
                const int n   = idx >> 3;
                const int kq  = idx & 7;
                const float* src = W + (size_t)(n0 + n) * K + kt + kq * 4;
                uint32_t sa = (uint32_t)__cvta_generic_to_shared(&s->rawB[st][idx]);
                asm volatile("cp.async.cg.shared.global [%0], [%1], 16;\n"
                             :: "r"(sa), "l"(src));
            }
        }
        asm volatile("cp.async.commit_group;\n");
    };

    // ---- convert raw stage -> bf16 hi/lo planes (reads own slots only)
    auto storeAB = [&](int bb, int st) {
#pragma unroll
        for (int j = 0; j < 4; j++) {
            const int idx = t + 256 * j;
            const int row = idx >> 3;
            const int kq  = idx & 7;
            float4 v = s->rawA[st][idx];
            uint32_t wh0, wl0, wh1, wl1;
            pack2_bf(v.x, v.y, wh0, wl0);
            pack2_bf(v.z, v.w, wh1, wl1);
            *reinterpret_cast<uint2*>(&s->Ah[bb][row][2 * kq]) = make_uint2(wh0, wh1);
            *reinterpret_cast<uint2*>(&s->Al[bb][row][2 * kq]) = make_uint2(wl0, wl1);
        }
        uint32_t* bp = s->Bp[bb];
        if (NN) {
            const int kp   = t >> 4;
            const int nq   = t & 15;
            const int ks16 = kp >> 3;
            const int pp   = kp & 7;
            const int breg = (pp >= 4) ? 1 : 0;
            const int tgk  = pp & 3;
            float4 r0 = s->rawB[st][t];
            float4 r1 = s->rawB[st][t + 256];
            const float e0[4] = {r0.x, r0.y, r0.z, r0.w};
            const float e1[4] = {r1.x, r1.y, r1.z, r1.w};
#pragma unroll
            for (int cc = 0; cc < 4; cc++) {
                const int n  = nq * 4 + cc;
                const int bi = (n >> 3) * 2 + ks16;
                uint32_t wh, wl;
                pack2_bf(e0[cc], e1[cc], wh, wl);
                uint32_t* base = bp + bi * 132 + ((n & 7) * 4 + tgk) * 4;
                base[breg]     = wh;
                base[breg + 2] = wl;
            }
        } else {
#pragma unroll
            for (int j = 0; j < 2; j++) {
                const int idx  = t + 256 * j;
                const int n    = idx >> 3;
                const int kq   = idx & 7;
                const int ks16 = kq >> 2;
                const int bi   = (n >> 3) * 2 + ks16;
                uint32_t* tb = bp + bi * 132 + ((n & 7) * 4) * 4;
                float4 v = s->rawB[st][idx];
                const float vals[4] = {v.x, v.y, v.z, v.w};
#pragma unroll
                for (int q = 0; q < 2; q++) {
                    const int pp   = (2 * kq + q) & 7;
                    const int breg = (pp >= 4) ? 1 : 0;
                    const int tgk  = pp & 3;
                    uint32_t wh, wl;
                    pack2_bf(vals[2 * q], vals[2 * q + 1], wh, wl);
                    uint32_t* base = tb + tgk * 4;
                    base[breg]     = wh;
                    base[breg + 2] = wl;
                }
            }
        }
    };
    auto compute = [&](int bb) {
        const uint32_t* bp = s->Bp[bb];
#pragma unroll
        for (int ks = 0; ks < 2; ks++) {
            const int base = ks * 8;
            uint32_t ah[2][4], al[2][4];
#pragma unroll
            for (int mi = 0; mi < 2; mi++) {
                const int rm = wm * 32 + mi * 16 + group;
                ah[mi][0] = s->Ah[bb][rm][base + tg];
                ah[mi][1] = s->Ah[bb][rm + 8][base + tg];
                ah[mi][2] = s->Ah[bb][rm][base + tg + 4];
                ah[mi][3] = s->Ah[bb][rm + 8][base + tg + 4];
                al[mi][0] = s->Al[bb][rm][base + tg];
                al[mi][1] = s->Al[bb][rm + 8][base + tg];
                al[mi][2] = s->Al[bb][rm][base + tg + 4];
                al[mi][3] = s->Al[bb][rm + 8][base + tg + 4];
            }
#pragma unroll
            for (int ni = 0; ni < 4; ni++) {
                const uint32_t* Bf = bp + ((wn * 4 + ni) * 2 + ks) * 132 + lane * 4;
                uint4 bv = *reinterpret_cast<const uint4*>(Bf);
#pragma unroll
                for (int mi = 0; mi < 2; mi++) {
                    mma_bf16(c[mi][ni], ah[mi], bv.x, bv.y);
                    mma_bf16(c[mi][ni], ah[mi], bv.z, bv.w);
                    mma_bf16(c[mi][ni], al[mi], bv.x, bv.y);
                }
            }
        }
    };

    const int nkb = kchunk >> 5;
    fillRaw(0, k0);
    if (nkb > 1) fillRaw(1, k0 + 32);

    for (int kb = 0; kb < nkb; kb++) {
        if (kb + 1 < nkb)
            asm volatile("cp.async.wait_group 1;\n" ::: "memory");
        else
            asm volatile("cp.async.wait_group 0;\n" ::: "memory");
        const int cur = kb & 1;
        storeAB(cur, cur);
        if (kb + 2 < nkb) fillRaw(cur, k0 + (kb + 2) * 32);
        __syncthreads();
        compute(cur);
        __syncthreads();
    }

    // ---- epilogue: optional 1/den row scale (context), bias on ky==0, v2 atomics
    float iv[2][2];
    if (XSEL == 2) {
#pragma unroll
        for (int mi = 0; mi < 2; mi++) {
            const int r0 = wm * 32 + mi * 16 + group;
            iv[mi][0] = 1.f / g_fden[r0];
            iv[mi][1] = 1.f / g_fden[r0 + 8];
        }
    }
    float* ob = (OUTSEL == 0) ? outp : (OUTSEL == 1 ? (float*)g_decq : (float*)g_u);
#pragma unroll
    for (int mi = 0; mi < 2; mi++) {
        const int row0 = wm * 32 + mi * 16 + group;
#pragma unroll
        for (int ni = 0; ni < 4; ni++) {
            const int col = n0 + wn * 32 + ni * 8 + 2 * tg;
            float b0 = 0.f, b1 = 0.f;
            if (bias != nullptr && ky == 0) {
                b0 = bias[col];
                b1 = bias[col + 1];
            }
            float v0 = c[mi][ni][0], v1 = c[mi][ni][1];
            float v2 = c[mi][ni][2], v3 = c[mi][ni][3];
            if (XSEL == 2) {
                v0 *= iv[mi][0]; v1 *= iv[mi][0];
                v2 *= iv[mi][1]; v3 *= iv[mi][1];
            }
            redadd2(ob + (size_t)row0 * N + col,       v0 + b0, v1 + b1);
            redadd2(ob + (size_t)(row0 + 8) * N + col, v2 + b0, v3 + b1);
        }
    }

    // ---- scratch lifecycle cleaning (grids are 256 CTAs -> ids 0..65535)
    if (CLEANSEL != 0) {
        const int id = (blockIdx.y * gridDim.x + blockIdx.x) * 256 + t;
        const float4 z = make_float4(0.f, 0.f, 0.f, 0.f);
        if (CLEANSEL == 1) {
            reinterpret_cast<float4*>(g_fpart)[id] = z;     // 65536 float4
            if (id < 32)
                reinterpret_cast<float4*>(g_fden)[id] = z;  // 128 floats
        } else {
            if (id < 32768)
                reinterpret_cast<float4*>(g_decq)[id] = z;  // 32768 float4
            reinterpret_cast<float4*>(g_u)[id] = z;         // 65536 float4
        }
    }
}

// =====================================================================
// Fused attention pass, per-pair decoupled cp.async pipelines.
// grid (BB, 2), 256 threads = 8 warps = 4 warp PAIRS.
// Epilogue red.adds the CTA partial into the SINGLE g_fpart plane and
// g_fden[b] (2 contributions per address -> IEEE-commutative).
// ALSO initializes out = bv (context GEMM's atomics need it pre-set).
// =====================================================================
__global__ void __launch_bounds__(256, 2)
fused_attn_kernel(const float* __restrict__ enc, const float* __restrict__ bq,
                  const float* __restrict__ bv, float* __restrict__ out) {
    const int b    = blockIdx.x;
    const int sp   = blockIdx.y;       // 0..1
    const int t    = threadIdx.x;      // 256
    const int warp = t >> 5;
    const int lane = t & 31;
    const int pair = warp >> 1;        // 0..3
    const int half = warp & 1;         // 0/1 : which half of the row
    const int lstart = sp * 98;
    const int nrows  = (98 - pair + 3) >> 2;   // pairs 0,1: 25; pairs 2,3: 24

    extern __shared__ float smf[];
    float* u_s = smf;                            // [2048]  (8KB)
    float* buf = smf + EE;                       // [4][PDEPTH][2048] (96KB)
    __shared__ float cred[8];
    __shared__ float dpair[4];
    __shared__ float pd[4][2][2];                // [pair][parity][half]
    __shared__ float c_sh;

    // ---- init out = bv : CTA (b,sp) covers 512 floats (128 float4)
    {
        const int cid = (b * 2 + sp) * 128;      // float4 base
        if (t < 128) {
            const int f = (cid + t);             // float4 idx into out
            reinterpret_cast<float4*>(out)[f] =
                *reinterpret_cast<const float4*>(bv + ((f & 255) * 4));
        }
    }

    // ---- stage u[b]
#pragma unroll
    for (int j = 0; j < 2; j++) {
        const int p = t + 256 * j;               // float4 index 0..511
        *reinterpret_cast<float4*>(u_s + 4 * p) =
            *reinterpret_cast<const float4*>(g_u + (size_t)b * EE + 4 * p);
    }

    // ---- c[b] = bq . dec_q[b] (fixed order)
    {
        const float* dq = g_decq + (size_t)b * AA;
        float cv = bq[t] * dq[t] + bq[t + 256] * dq[t + 256]
                 + bq[t + 512] * dq[t + 512] + bq[t + 768] * dq[t + 768];
#pragma unroll
        for (int o = 16; o > 0; o >>= 1) cv += __shfl_xor_sync(0xffffffffu, cv, o);
        if (lane == 0) cred[warp] = cv;
    }
    __syncthreads();
    if (t == 0) {
        float tot = 0.f;
        for (int i = 0; i < 8; i++) tot += cred[i];
        c_sh = tot;
    }
    __syncthreads();
    const float c_b = c_sh;

    const float* encb = enc + (size_t)b * LL * EE;
    float* mybuf = buf + (size_t)(pair * PDEPTH) * EE;     // this pair's slots
    const int fo = half * 256 + lane;                       // float4 offset base

    auto fill = [&](int i) {
        if (i < nrows) {
            const int l = lstart + pair + 4 * i;
            const float4* src = reinterpret_cast<const float4*>(encb + (size_t)l * EE) + fo;
            uint32_t sa = (uint32_t)__cvta_generic_to_shared(mybuf + (size_t)(i % PDEPTH) * EE)
                        + (uint32_t)fo * 16u;
#pragma unroll
            for (int q = 0; q < 8; q++) {
                asm volatile("cp.async.cg.shared.global [%0], [%1], 16;\n"
                             :: "r"(sa + q * 512u), "l"(src + q * 32));
            }
        }
        asm volatile("cp.async.commit_group;\n");
    };

    float4 ma[8];
#pragma unroll
    for (int i = 0; i < 8; i++) ma[i] = make_float4(0.f, 0.f, 0.f, 0.f);
    float den = 0.f;

    const float4* us4 = reinterpret_cast<const float4*>(u_s) + half * 256;
    const int barid = pair + 1;                   // named barriers 1..4, 64 thr

    fill(0); fill(1); fill(2);

    for (int i = 0; i < nrows; i++) {
        asm volatile("cp.async.wait_group %0;\n" :: "n"(PDEPTH - 1) : "memory");
        const float4* slot = reinterpret_cast<const float4*>(
            mybuf + (size_t)(i % PDEPTH) * EE) + fo;
        float4 x[8];
#pragma unroll
        for (int q = 0; q < 8; q++) x[q] = slot[q * 32];
        float d = 0.f;
#pragma unroll
        for (int q = 0; q < 8; q++) {
            float4 uu = us4[lane + 32 * q];
            d += x[q].x * uu.x + x[q].y * uu.y + x[q].z * uu.z + x[q].w * uu.w;
        }
#pragma unroll
        for (int o = 16; o > 0; o >>= 1) d += __shfl_xor_sync(0xffffffffu, d, o);
        const int par = i & 1;
        if (lane == 0) pd[pair][par][half] = d;
        asm volatile("bar.sync %0, 64;" :: "r"(barid) : "memory");
        const float z  = pd[pair][par][0] + pd[pair][par][1] + c_b;
        const float th = 1.f - __fdividef(2.f, __expf(2.f * z) + 1.f);
        const float w  = __expf(th);
        if (half == 0) den += w;
#pragma unroll
        for (int q = 0; q < 8; q++) {
            ma[q].x += w * x[q].x; ma[q].y += w * x[q].y;
            ma[q].z += w * x[q].z; ma[q].w += w * x[q].w;
        }
        fill(i + PDEPTH);
    }

    asm volatile("cp.async.wait_group 0;\n" ::: "memory");
    __syncthreads();

    float* sacc = buf;                            // [4][2048]
    float4* sw = reinterpret_cast<float4*>(sacc + (size_t)pair * EE) + fo;
#pragma unroll
    for (int q = 0; q < 8; q++) sw[q * 32] = ma[q];
    if (half == 0 && lane == 0) dpair[pair] = den;
    __syncthreads();

    float* pp = g_fpart + (size_t)b * EE;
#pragma unroll
    for (int j = 0; j < 2; j++) {
        const int p = t + 256 * j;                // float4 index 0..511
        float4 a = reinterpret_cast<const float4*>(sacc)[p];
#pragma unroll
        for (int q = 1; q < 4; q++) {
            float4 v = reinterpret_cast<const float4*>(sacc + (size_t)q * EE)[p];
            a.x += v.x; a.y += v.y; a.z += v.z; a.w += v.w;
        }
        redadd2(pp + 4 * p,     a.x, a.y);
        redadd2(pp + 4 * p + 2, a.z, a.w);
    }
    if (t == 0) redadd(&g_fden[b], dpair[0] + dpair[1] + dpair[2] + dpair[3]);
}

// =====================================================================
// Launcher
// =====================================================================
extern "C" void kernel_launch(void* const* d_in, const int* in_sizes, int n_in,
                              void* d_out, int out_size) {
    const float* enc = (const float*)d_in[0];  // [128,196,2048]
    const float* dh  = (const float*)d_in[1];  // [128,1024]
    const float* Wq  = (const float*)d_in[2];  // [1024,2048]  (A,E)
    const float* bq  = (const float*)d_in[3];  // [1024]
    const float* Wv  = (const float*)d_in[4];  // [1024,2048]  (A,E)
    const float* bv  = (const float*)d_in[5];  // [1024]
    const float* Wd  = (const float*)d_in[6];  // [1024,1024]  (A,D)
    const float* bd  = (const float*)d_in[7];  // [1024]
    float* out = (float*)d_out;                // [128,1024]

    const int gsm = (int)sizeof(SmemGemm);                  // ~105KB dynamic
    const int fsm = (EE + 4 * PDEPTH * EE) * 4;             // 8 + 96 = 104KB
    cudaFuncSetAttribute(gemm_tc<false, 0, 1, 1>, cudaFuncAttributeMaxDynamicSharedMemorySize, gsm);
    cudaFuncSetAttribute(gemm_tc<true, 1, 2, 0>,  cudaFuncAttributeMaxDynamicSharedMemorySize, gsm);
    cudaFuncSetAttribute(gemm_tc<false, 2, 0, 2>, cudaFuncAttributeMaxDynamicSharedMemorySize, gsm);
    cudaFuncSetAttribute(fused_attn_kernel,       cudaFuncAttributeMaxDynamicSharedMemorySize, fsm);

    // 1) g_decq += h @ Wd^T (+bd on split 0); zero g_fpart/g_fden for fused
    //    (NT, K=1024, split 16 -> 256 CTAs)
    gemm_tc<false, 0, 1, 1><<<dim3(AA / 64, 16), 256, gsm>>>(
        dh, Wd, nullptr, bd, DD, AA, DD / 16);

    // 2) g_u += dec_q @ Wq   (NN, K=1024, split 8 -> 256 CTAs)
    gemm_tc<true, 1, 2, 0><<<dim3(EE / 64, USPLIT), 256, gsm>>>(
        nullptr, Wq, nullptr, nullptr, AA, EE, AA / USPLIT);

    // 3) fused: out=bv init + c + energies + weights + weighted encoder sum
    //    (red.add into single-plane g_fpart + g_fden)
    fused_attn_kernel<<<dim3(BB, 2), 256, fsm>>>(enc, bq, bv, out);

    // 4) out += (fpart @ Wv^T) * inv(row) (+bv preset); zero g_decq/g_u
    //    (NT, K=2048, split 16 -> 256 CTAs)
    gemm_tc<false, 2, 0, 2><<<dim3(AA / 64, 16), 256, gsm>>>(
        nullptr, Wv, out, nullptr, EE, AA, EE / 16);
}

// round 17
// speedup vs baseline: 1.0557x; 1.0557x over previous
#include <cuda_runtime.h>
#include <cstdint>

// Problem constants
#define BB   128   // batch
#define LL   196   // encoder length
#define EE   2048  // encoder dim
#define DD   1024  // decoder dim
#define AA   1024  // attention dim
#define USPLIT 8   // split-K of the u GEMM -> 32x8 = 256 CTAs
#define PDEPTH 3   // per-pair pipeline depth (row slots) in fused kernel

// ---------------- device scratch (no allocations allowed) ----------------
// g_decq / g_u are zero at module load and re-zeroed by the LAST kernel of
// every run (context GEMM) -> each run starts with zeroed accumulators.
__device__ float g_decq[BB * AA];        // Wd @ h + bd           [128,1024]
__device__ float g_u[BB * EE];           // dec_q @ Wq            [128,2048]
__device__ float g_fpart[2 * BB * EE];   // fused partial sums (unnormalized)
__device__ float g_fden[2 * BB];         // fused partial denominators

// ---------------- helpers ----------------
__device__ __forceinline__ void redadd2(float* p, float a, float b) {
    asm volatile("red.global.add.v2.f32 [%0], {%1, %2};"
                 :: "l"(p), "f"(a), "f"(b) : "memory");
}
__device__ __forceinline__ void pdl_wait() {
    asm volatile("griddepcontrol.wait;" ::: "memory");
}
__device__ __forceinline__ void pdl_trigger() {
    asm volatile("griddepcontrol.launch_dependents;" ::: "memory");
}

__device__ __forceinline__ void pack2_bf(float x0, float x1,
                                         uint32_t& wh, uint32_t& wl) {
    asm("cvt.rn.bf16x2.f32 %0, %1, %2;" : "=r"(wh) : "f"(x1), "f"(x0));
    float h0 = __uint_as_float(wh << 16);
    float h1 = __uint_as_float(wh & 0xffff0000u);
    float l0 = x0 - h0;
    float l1 = x1 - h1;
    asm("cvt.rn.bf16x2.f32 %0, %1, %2;" : "=r"(wl) : "f"(l1), "f"(l0));
}

__device__ __forceinline__ void mma_bf16(float* c, const uint32_t* a,
                                         uint32_t b0, uint32_t b1) {
    asm volatile(
        "mma.sync.aligned.m16n8k16.row.col.f32.bf16.bf16.f32 "
        "{%0,%1,%2,%3}, {%4,%5,%6,%7}, {%8,%9}, {%0,%1,%2,%3};"
        : "+f"(c[0]), "+f"(c[1]), "+f"(c[2]), "+f"(c[3])
        : "r"(a[0]), "r"(a[1]), "r"(a[2]), "r"(a[3]), "r"(b0), "r"(b1));
}

// Smem: A planes [row][kpair] stride 20 (conflict-free frag reads),
// B packed fragment-major.
struct SmemGemm {
    uint32_t Ah[2][128][20];
    uint32_t Al[2][128][20];
    uint32_t Bp[2][16 * 132];
};

// =====================================================================
// Tensor-core bf16x3 GEMM with ATOMIC (v2) split-K epilogue + PDL:
//   dest[m][n] += sum_{k in chunk} X[m,k] * W(k,n)  (+ bias on ky==0 split)
//   NN=true : W is [K,N] row-major;  NN=false: W is [N,K] row-major
// XSEL: 0 -> X param, 1 -> g_decq, 2 -> (g_fpart[0]+g_fpart[1]) * inv_row
// OUTSEL: 0 -> outp param, 1 -> g_decq, 2 -> g_u
// CLEAN: after epilogue, zero g_decq/g_u (context GEMM only, 256 CTAs).
// WAIT: consumer kernel -> prefetch W (independent) then griddepcontrol.wait
//       before touching producer data. All kernels trigger dependents after
//       their epilogue.
// =====================================================================
template <bool NN, int XSEL, int OUTSEL, bool CLEAN, bool WAIT>
__global__ void __launch_bounds__(256, 2)
gemm_tc(const float* __restrict__ Xp, const float* __restrict__ W,
        float* __restrict__ outp, const float* __restrict__ bias,
        int K, int N, int kchunk) {
    extern __shared__ SmemGemm sm_g[];
    SmemGemm* s = sm_g;

    const float* X = (XSEL == 1) ? (const float*)g_decq : Xp;

    const int t     = threadIdx.x;
    const int warp  = t >> 5;
    const int lane  = t & 31;
    const int group = lane >> 2;
    const int tg    = lane & 3;
    const int wm    = warp & 3;
    const int wn    = warp >> 2;
    const int n0    = blockIdx.x * 64;
    const int ky    = blockIdx.y;
    const int k0    = ky * kchunk;

    float c[2][4][4];
#pragma unroll
    for (int mi = 0; mi < 2; mi++)
#pragma unroll
        for (int ni = 0; ni < 4; ni++)
#pragma unroll
            for (int r = 0; r < 4; r++) c[mi][ni][r] = 0.f;

    float4 ra[4];
    float4 rb[2];

    auto loadA = [&](int kt) {
#pragma unroll
        for (int j = 0; j < 4; j++) {
            const int idx = t + 256 * j;
            const int row = idx >> 3;
            const int kq  = idx & 7;
            if (XSEL == 2) {
                float4 p0 = *reinterpret_cast<const float4*>(
                    g_fpart + (size_t)row * EE + kt + kq * 4);
                float4 p1 = *reinterpret_cast<const float4*>(
                    g_fpart + (size_t)(BB + row) * EE + kt + kq * 4);
                ra[j] = make_float4(p0.x + p1.x, p0.y + p1.y,
                                    p0.z + p1.z, p0.w + p1.w);
            } else {
                ra[j] = *reinterpret_cast<const float4*>(X + (size_t)row * K + kt + kq * 4);
            }
        }
    };
    auto loadB = [&](int kt) {
        if (NN) {
            const int kp = t >> 4;
            const int nq = t & 15;
            rb[0] = *reinterpret_cast<const float4*>(W + (size_t)(kt + 2 * kp) * N + n0 + nq * 4);
            rb[1] = *reinterpret_cast<const float4*>(W + (size_t)(kt + 2 * kp + 1) * N + n0 + nq * 4);
        } else {
#pragma unroll
            for (int j = 0; j < 2; j++) {
                const int idx = t + 256 * j;
                const int n   = idx >> 3;
                const int kq  = idx & 7;
                rb[j] = *reinterpret_cast<const float4*>(W + (size_t)(n0 + n) * K + kt + kq * 4);
            }
        }
    };
    auto storeAB = [&](int bb) {
#pragma unroll
        for (int j = 0; j < 4; j++) {
            const int idx = t + 256 * j;
            const int row = idx >> 3;
            const int kq  = idx & 7;
            uint32_t wh0, wl0, wh1, wl1;
            pack2_bf(ra[j].x, ra[j].y, wh0, wl0);
            pack2_bf(ra[j].z, ra[j].w, wh1, wl1);
            *reinterpret_cast<uint2*>(&s->Ah[bb][row][2 * kq]) = make_uint2(wh0, wh1);
            *reinterpret_cast<uint2*>(&s->Al[bb][row][2 * kq]) = make_uint2(wl0, wl1);
        }
        uint32_t* bp = s->Bp[bb];
        if (NN) {
            const int kp   = t >> 4;
            const int nq   = t & 15;
            const int ks16 = kp >> 3;
            const int pp   = kp & 7;
            const int breg = (pp >= 4) ? 1 : 0;
            const int tgk  = pp & 3;
            const float e0[4] = {rb[0].x, rb[0].y, rb[0].z, rb[0].w};
            const float e1[4] = {rb[1].x, rb[1].y, rb[1].z, rb[1].w};
#pragma unroll
            for (int cc = 0; cc < 4; cc++) {
                const int n  = nq * 4 + cc;
                const int bi = (n >> 3) * 2 + ks16;
                uint32_t wh, wl;
                pack2_bf(e0[cc], e1[cc], wh, wl);
                uint32_t* base = bp + bi * 132 + ((n & 7) * 4 + tgk) * 4;
                base[breg]     = wh;
                base[breg + 2] = wl;
            }
        } else {
#pragma unroll
            for (int j = 0; j < 2; j++) {
                const int idx  = t + 256 * j;
                const int n    = idx >> 3;
                const int kq   = idx & 7;
                const int ks16 = kq >> 2;
                const int bi   = (n >> 3) * 2 + ks16;
                uint32_t* tb = bp + bi * 132 + ((n & 7) * 4) * 4;
                const float vals[4] = {rb[j].x, rb[j].y, rb[j].z, rb[j].w};
#pragma unroll
                for (int q = 0; q < 2; q++) {
                    const int pp   = (2 * kq + q) & 7;
                    const int breg = (pp >= 4) ? 1 : 0;
                    const int tgk  = pp & 3;
                    uint32_t wh, wl;
                    pack2_bf(vals[2 * q], vals[2 * q + 1], wh, wl);
                    uint32_t* base = tb + tgk * 4;
                    base[breg]     = wh;
                    base[breg + 2] = wl;
                }
            }
        }
    };
    auto compute = [&](int bb) {
        const uint32_t* bp = s->Bp[bb];
#pragma unroll
        for (int ks = 0; ks < 2; ks++) {
            const int base = ks * 8;
            uint32_t ah[2][4], al[2][4];
#pragma unroll
            for (int mi = 0; mi < 2; mi++) {
                const int rm = wm * 32 + mi * 16 + group;
                ah[mi][0] = s->Ah[bb][rm][base + tg];
                ah[mi][1] = s->Ah[bb][rm + 8][base + tg];
                ah[mi][2] = s->Ah[bb][rm][base + tg + 4];
                ah[mi][3] = s->Ah[bb][rm + 8][base + tg + 4];
                al[mi][0] = s->Al[bb][rm][base + tg];
                al[mi][1] = s->Al[bb][rm + 8][base + tg];
                al[mi][2] = s->Al[bb][rm][base + tg + 4];
                al[mi][3] = s->Al[bb][rm + 8][base + tg + 4];
            }
#pragma unroll
            for (int ni = 0; ni < 4; ni++) {
                const uint32_t* Bf = bp + ((wn * 4 + ni) * 2 + ks) * 132 + lane * 4;
                uint4 bv = *reinterpret_cast<const uint4*>(Bf);
#pragma unroll
                for (int mi = 0; mi < 2; mi++) {
                    mma_bf16(c[mi][ni], ah[mi], bv.x, bv.y);
                    mma_bf16(c[mi][ni], ah[mi], bv.z, bv.w);
                    mma_bf16(c[mi][ni], al[mi], bv.x, bv.y);
                }
            }
        }
    };

    // ---- independent prologue: prefetch first W tile (input, no producer dep)
    loadB(k0);
    // ---- wait for producer data before touching X / g_fden
    if (WAIT) pdl_wait();

    float invj[2][2];   // per-row 1/sum(w) for the context GEMM (XSEL==2)
    if (XSEL == 2) {
#pragma unroll
        for (int mi = 0; mi < 2; mi++) {
            const int r0 = wm * 32 + mi * 16 + group;
            invj[mi][0] = 1.f / (g_fden[r0] + g_fden[BB + r0]);
            invj[mi][1] = 1.f / (g_fden[r0 + 8] + g_fden[BB + r0 + 8]);
        }
    }

    loadA(k0);
    storeAB(0);
    __syncthreads();

    const int nkb = kchunk >> 5;
    for (int kb = 0; kb < nkb; kb++) {
        const int cur = kb & 1;
        if (kb + 1 < nkb) {
            loadA(k0 + (kb + 1) * 32);
            loadB(k0 + (kb + 1) * 32);
        }
        compute(cur);
        if (kb + 1 < nkb) storeAB(cur ^ 1);
        __syncthreads();
    }

    // ---- bias fold (once, on the ky==0 split) + row scale + v2 atomics
    float* ob = (OUTSEL == 0) ? outp : (OUTSEL == 1 ? (float*)g_decq : (float*)g_u);
#pragma unroll
    for (int mi = 0; mi < 2; mi++) {
        const int row0 = wm * 32 + mi * 16 + group;
#pragma unroll
        for (int ni = 0; ni < 4; ni++) {
            const int col = n0 + wn * 32 + ni * 8 + 2 * tg;
            float b0 = 0.f, b1 = 0.f;
            if (bias != nullptr && ky == 0) {
                b0 = bias[col];
                b1 = bias[col + 1];
            }
            float v0 = c[mi][ni][0], v1 = c[mi][ni][1];
            float v2 = c[mi][ni][2], v3 = c[mi][ni][3];
            if (XSEL == 2) {
                v0 *= invj[mi][0]; v1 *= invj[mi][0];
                v2 *= invj[mi][1]; v3 *= invj[mi][1];
            }
            redadd2(ob + (size_t)row0 * N + col,       v0 + b0, v1 + b1);
            redadd2(ob + (size_t)(row0 + 8) * N + col, v2 + b0, v3 + b1);
        }
    }

    // ---- allow dependent kernel to launch (all dependent data written)
    pdl_trigger();

    // ---- self-clean scratch for the next run (context GEMM only, 256 CTAs).
    // Protected by graph stream-order (next replay's first kernel has no PDL).
    if (CLEAN) {
        const int id = (blockIdx.y * gridDim.x + blockIdx.x) * 256 + t;  // 0..65535
        const float4 z = make_float4(0.f, 0.f, 0.f, 0.f);
        if (id < 32768)
            reinterpret_cast<float4*>(g_decq)[id] = z;   // 32768 float4
        reinterpret_cast<float4*>(g_u)[id] = z;          // 65536 float4
    }
}

// =====================================================================
// Fused attention pass, per-pair decoupled cp.async pipelines + PDL.
// grid (BB, 2), 256 threads = 8 warps = 4 warp PAIRS.
// Independent prologue BEFORE griddepcontrol.wait: out=bv init and the
// first PDEPTH enc fill groups (enc/bv are inputs, no producer dep).
// ALSO initializes out = bv (context GEMM's atomics need it pre-set).
// =====================================================================
__global__ void __launch_bounds__(256, 2)
fused_attn_kernel(const float* __restrict__ enc, const float* __restrict__ bq,
                  const float* __restrict__ bv, float* __restrict__ out) {
    const int b    = blockIdx.x;
    const int sp   = blockIdx.y;       // 0..1
    const int t    = threadIdx.x;      // 256
    const int warp = t >> 5;
    const int lane = t & 31;
    const int pair = warp >> 1;        // 0..3
    const int half = warp & 1;         // 0/1 : which half of the row
    const int lstart = sp * 98;
    const int nrows  = (98 - pair + 3) >> 2;   // pairs 0,1: 25; pairs 2,3: 24

    extern __shared__ float smf[];
    float* u_s = smf;                            // [2048]  (8KB)
    float* buf = smf + EE;                       // [4][PDEPTH][2048] (96KB)
    __shared__ float cred[8];
    __shared__ float dpair[4];
    __shared__ float pd[4][2][2];                // [pair][parity][half]
    __shared__ float c_sh;

    const float* encb = enc + (size_t)b * LL * EE;
    float* mybuf = buf + (size_t)(pair * PDEPTH) * EE;     // this pair's slots
    const int fo = half * 256 + lane;                       // float4 offset base

    auto fill = [&](int i) {
        if (i < nrows) {
            const int l = lstart + pair + 4 * i;
            const float4* src = reinterpret_cast<const float4*>(encb + (size_t)l * EE) + fo;
            uint32_t sa = (uint32_t)__cvta_generic_to_shared(mybuf + (size_t)(i % PDEPTH) * EE)
                        + (uint32_t)fo * 16u;
#pragma unroll
            for (int q = 0; q < 8; q++) {
                asm volatile("cp.async.cg.shared.global [%0], [%1], 16;\n"
                             :: "r"(sa + q * 512u), "l"(src + q * 32));
            }
        }
        asm volatile("cp.async.commit_group;\n");
    };

    // ---- independent prologue (no producer dependency): out=bv + enc fills
    {
        const int cid = (b * 2 + sp) * 128;      // float4 base
        if (t < 128) {
            const int f = (cid + t);             // float4 idx into out
            reinterpret_cast<float4*>(out)[f] =
                *reinterpret_cast<const float4*>(bv + ((f & 255) * 4));
        }
    }
    fill(0); fill(1); fill(2);

    // ---- wait for u-GEMM (g_u, g_decq) to be complete
    pdl_wait();

    // ---- stage u[b]
#pragma unroll
    for (int j = 0; j < 2; j++) {
        const int p = t + 256 * j;               // float4 index 0..511
        *reinterpret_cast<float4*>(u_s + 4 * p) =
            *reinterpret_cast<const float4*>(g_u + (size_t)b * EE + 4 * p);
    }

    // ---- c[b] = bq . dec_q[b] (fixed order)
    {
        const float* dq = g_decq + (size_t)b * AA;
        float cv = bq[t] * dq[t] + bq[t + 256] * dq[t + 256]
                 + bq[t + 512] * dq[t + 512] + bq[t + 768] * dq[t + 768];
#pragma unroll
        for (int o = 16; o > 0; o >>= 1) cv += __shfl_xor_sync(0xffffffffu, cv, o);
        if (lane == 0) cred[warp] = cv;
    }
    __syncthreads();
    if (t == 0) {
        float tot = 0.f;
        for (int i = 0; i < 8; i++) tot += cred[i];
        c_sh = tot;
    }
    __syncthreads();
    const float c_b = c_sh;

    float4 ma[8];
#pragma unroll
    for (int i = 0; i < 8; i++) ma[i] = make_float4(0.f, 0.f, 0.f, 0.f);
    float den = 0.f;

    const float4* us4 = reinterpret_cast<const float4*>(u_s) + half * 256;
    const int barid = pair + 1;                   // named barriers 1..4, 64 thr

    for (int i = 0; i < nrows; i++) {
        asm volatile("cp.async.wait_group %0;\n" :: "n"(PDEPTH - 1) : "memory");
        const float4* slot = reinterpret_cast<const float4*>(
            mybuf + (size_t)(i % PDEPTH) * EE) + fo;
        float4 x[8];
#pragma unroll
        for (int q = 0; q < 8; q++) x[q] = slot[q * 32];
        float d = 0.f;
#pragma unroll
        for (int q = 0; q < 8; q++) {
            float4 uu = us4[lane + 32 * q];
            d += x[q].x * uu.x + x[q].y * uu.y + x[q].z * uu.z + x[q].w * uu.w;
        }
#pragma unroll
        for (int o = 16; o > 0; o >>= 1) d += __shfl_xor_sync(0xffffffffu, d, o);
        const int par = i & 1;
        if (lane == 0) pd[pair][par][half] = d;
        asm volatile("bar.sync %0, 64;" :: "r"(barid) : "memory");
        const float z  = pd[pair][par][0] + pd[pair][par][1] + c_b;
        const float th = 1.f - __fdividef(2.f, __expf(2.f * z) + 1.f);
        const float w  = __expf(th);
        if (half == 0) den += w;
#pragma unroll
        for (int q = 0; q < 8; q++) {
            ma[q].x += w * x[q].x; ma[q].y += w * x[q].y;
            ma[q].z += w * x[q].z; ma[q].w += w * x[q].w;
        }
        fill(i + PDEPTH);
    }

    asm volatile("cp.async.wait_group 0;\n" ::: "memory");
    __syncthreads();

    float* sacc = buf;                            // [4][2048]
    float4* sw = reinterpret_cast<float4*>(sacc + (size_t)pair * EE) + fo;
#pragma unroll
    for (int q = 0; q < 8; q++) sw[q * 32] = ma[q];
    if (half == 0 && lane == 0) dpair[pair] = den;
    __syncthreads();

    float* pp = g_fpart + ((size_t)sp * BB + b) * EE;
#pragma unroll
    for (int j = 0; j < 2; j++) {
        const int p = t + 256 * j;                // float4 index 0..511
        float4 a = reinterpret_cast<const float4*>(sacc)[p];
#pragma unroll
        for (int q = 1; q < 4; q++) {
            float4 v = reinterpret_cast<const float4*>(sacc + (size_t)q * EE)[p];
            a.x += v.x; a.y += v.y; a.z += v.z; a.w += v.w;
        }
        reinterpret_cast<float4*>(pp)[p] = a;
    }
    if (t == 0) g_fden[sp * BB + b] = dpair[0] + dpair[1] + dpair[2] + dpair[3];

    // ---- allow context GEMM to launch
    pdl_trigger();
}

// =====================================================================
// Launcher — PDL-chained: decq -> u -> fused -> context
// =====================================================================
extern "C" void kernel_launch(void* const* d_in, const int* in_sizes, int n_in,
                              void* d_out, int out_size) {
    const float* enc = (const float*)d_in[0];  // [128,196,2048]
    const float* dh  = (const float*)d_in[1];  // [128,1024]
    const float* Wq  = (const float*)d_in[2];  // [1024,2048]  (A,E)
    const float* bq  = (const float*)d_in[3];  // [1024]
    const float* Wv  = (const float*)d_in[4];  // [1024,2048]  (A,E)
    const float* bv  = (const float*)d_in[5];  // [1024]
    const float* Wd  = (const float*)d_in[6];  // [1024,1024]  (A,D)
    const float* bd  = (const float*)d_in[7];  // [1024]
    float* out = (float*)d_out;                // [128,1024]

    const int gsm = (int)sizeof(SmemGemm);                  // ~57KB dynamic
    const int fsm = (EE + 4 * PDEPTH * EE) * 4;             // 8 + 96 = 104KB
    cudaFuncSetAttribute(gemm_tc<false, 0, 1, false, false>, cudaFuncAttributeMaxDynamicSharedMemorySize, gsm);
    cudaFuncSetAttribute(gemm_tc<true, 1, 2, false, true>,   cudaFuncAttributeMaxDynamicSharedMemorySize, gsm);
    cudaFuncSetAttribute(gemm_tc<false, 2, 0, true, true>,   cudaFuncAttributeMaxDynamicSharedMemorySize, gsm);
    cudaFuncSetAttribute(fused_attn_kernel,                  cudaFuncAttributeMaxDynamicSharedMemorySize, fsm);

    cudaLaunchAttribute pa[1];
    pa[0].id = cudaLaunchAttributeProgrammaticStreamSerialization;
    pa[0].val.programmaticStreamSerializationAllowed = 1;

    // 1) g_decq += h @ Wd^T (+bd on split 0)  (NT, K=1024, split 16 -> 256 CTAs)
    gemm_tc<false, 0, 1, false, false><<<dim3(AA / 64, 16), 256, gsm>>>(
        dh, Wd, nullptr, bd, DD, AA, DD / 16);

    // 2) g_u += dec_q @ Wq  (NN, K=1024, split 8 -> 256 CTAs) [PDL]
    {
        cudaLaunchConfig_t cfg = {};
        cfg.gridDim = dim3(EE / 64, USPLIT);
        cfg.blockDim = dim3(256);
        cfg.dynamicSmemBytes = gsm;
        cfg.stream = 0;
        cfg.attrs = pa;
        cfg.numAttrs = 1;
        cudaLaunchKernelEx(&cfg, gemm_tc<true, 1, 2, false, true>,
                           (const float*)nullptr, Wq, (float*)nullptr,
                           (const float*)nullptr, (int)AA, (int)EE, (int)(AA / USPLIT));
    }

    // 3) fused: out=bv init + c + energies + weights + weighted sum [PDL]
    {
        cudaLaunchConfig_t cfg = {};
        cfg.gridDim = dim3(BB, 2);
        cfg.blockDim = dim3(256);
        cfg.dynamicSmemBytes = fsm;
        cfg.stream = 0;
        cfg.attrs = pa;
        cfg.numAttrs = 1;
        cudaLaunchKernelEx(&cfg, fused_attn_kernel, enc, bq, bv, out);
    }

    // 4) out += ((P0+P1)*inv) @ Wv^T ; then zero g_decq/g_u [PDL]
    {
        cudaLaunchConfig_t cfg = {};
        cfg.gridDim = dim3(AA / 64, 16);
        cfg.blockDim = dim3(256);
        cfg.dynamicSmemBytes = gsm;
        cfg.stream = 0;
        cfg.attrs = pa;
        cfg.numAttrs = 1;
        cudaLaunchKernelEx(&cfg, gemm_tc<false, 2, 0, true, true>,
                           (const float*)nullptr, Wv, out,
                           (const float*)nullptr, (int)EE, (int)AA, (int)(EE / 16));
    }
}